// round 2
// baseline (speedup 1.0000x reference)
#include <cuda_runtime.h>
#include <cuda_fp16.h>

#define D 128
#define TILE_ROWS 64
#define TILE_PAIRS 32
#define NTHREADS 256
#define PAIR_PAD 129   /* ull stride per pair-row (pad to break bank conflicts on stores) */

#define SMEM_BYTES (65536 /*PiT*/ + 65536 /*Pi*/ + 33024 /*Xs*/ + 33024 /*Vs*/ \
                    + 256 /*inv*/ + 256 /*nq*/ + 64 /*bnd*/ + 64 /*cent*/)

// ---- packed f32x2 helpers (Blackwell sm_103a FFMA2) ----
__device__ __forceinline__ unsigned long long splat2(float v) {
    unsigned long long r;
    asm("mov.b64 %0, {%1, %1};" : "=l"(r) : "f"(v));
    return r;
}
__device__ __forceinline__ void fma2(unsigned long long &d, unsigned long long a,
                                     unsigned long long b) {
    asm("fma.rn.f32x2 %0, %1, %2, %0;" : "+l"(d) : "l"(a), "l"(b));
}
__device__ __forceinline__ float2 unpack2(unsigned long long v) {
    float2 f;
    asm("mov.b64 {%0, %1}, %2;" : "=f"(f.x), "=f"(f.y) : "l"(v));
    return f;
}
__device__ __forceinline__ unsigned long long pack2(float x, float y) {
    unsigned long long r;
    asm("mov.b64 %0, {%1, %2};" : "=l"(r) : "f"(x), "f"(y));
    return r;
}

extern "C" __global__ void __launch_bounds__(NTHREADS, 1)
tq_kernel(const float* __restrict__ x, const float* __restrict__ Pi,
          const float* __restrict__ cent, const float* __restrict__ bnd,
          float* __restrict__ out, int nrows, int ntiles)
{
    extern __shared__ char smem[];
    float* PiT_s = (float*)smem;                                   // [128][128]  Pi^T
    float* Pi_s  = (float*)(smem + 65536);                         // [128][128]  Pi
    unsigned long long* Xs = (unsigned long long*)(smem + 131072); // [32][129] row-pairs
    unsigned long long* Vs = Xs + TILE_PAIRS * PAIR_PAD;           // [32][129] row-pairs
    float* inv2 = (float*)(Vs + TILE_PAIRS * PAIR_PAD);            // [64] 1/(norm+eps)
    float* nq2  = inv2 + 64;                                       // [64] fp16-roundtrip norm
    float* sI   = nq2 + 64;                                        // [15] interior boundaries
    float* sC   = sI + 16;                                         // [16] centroids

    const int t = threadIdx.x;
    const int w = t >> 5;
    const int l = t & 31;

    // ---------------- one-time setup: tables + Pi / Pi^T staging ----------------
    if (t < 16) sC[t] = cent[t];
    if (t < 15) sI[t] = bnd[t + 1];
    {
        int j  = t >> 1;
        int k0 = (t & 1) * 64;
        const float4* src = (const float4*)(Pi + j * D + k0);
        #pragma unroll
        for (int i = 0; i < 16; i++) {
            float4 v = src[i];
            *(float4*)(Pi_s + j * D + k0 + 4 * i) = v;
            int kk = k0 + 4 * i;
            PiT_s[(kk + 0) * D + j] = v.x;
            PiT_s[(kk + 1) * D + j] = v.y;
            PiT_s[(kk + 2) * D + j] = v.z;
            PiT_s[(kk + 3) * D + j] = v.w;
        }
    }
    __syncthreads();

    const int pgbase  = w * 4;          // this warp's 4 row-pairs
    const int r_local = t >> 2;         // staging: row in tile (0..63)
    const int pg_st   = r_local >> 1;
    const int half    = r_local & 1;
    const int kc      = (t & 3) * 32;   // staging: k-chunk

    for (int tile = blockIdx.x; tile < ntiles; tile += gridDim.x) {
        const int row0 = tile * TILE_ROWS;

        // ---------------- stage X tile (pair-interleaved) + row norms ----------------
        {
            int row = row0 + r_local;
            float s = 0.f;
            float* dstf = (float*)Xs;
            if (row < nrows) {
                const float4* xr = (const float4*)(x + (size_t)row * D + kc);
                #pragma unroll
                for (int i = 0; i < 8; i++) {
                    float4 v = xr[i];
                    s += v.x * v.x + v.y * v.y + v.z * v.z + v.w * v.w;
                    int base = (pg_st * PAIR_PAD + kc + 4 * i) * 2 + half;
                    dstf[base + 0] = v.x;
                    dstf[base + 2] = v.y;
                    dstf[base + 4] = v.z;
                    dstf[base + 6] = v.w;
                }
            } else {
                #pragma unroll
                for (int i = 0; i < 8; i++) {
                    int base = (pg_st * PAIR_PAD + kc + 4 * i) * 2 + half;
                    dstf[base + 0] = 0.f; dstf[base + 2] = 0.f;
                    dstf[base + 4] = 0.f; dstf[base + 6] = 0.f;
                }
            }
            s += __shfl_xor_sync(0xffffffffu, s, 1);
            s += __shfl_xor_sync(0xffffffffu, s, 2);
            if ((t & 3) == 0) {
                float norm = sqrtf(s);
                inv2[pg_st * 2 + half] = 1.0f / (norm + 1e-8f);
                nq2[pg_st * 2 + half]  = __half2float(__float2half_rn(norm));
            }
        }
        __syncwarp();

        // ---------------- GEMM1: R[m,j] = sum_k X[m,k] * Pi[j,k]  (PiT in smem) ----------------
        unsigned long long acc[4][4];
        #pragma unroll
        for (int p = 0; p < 4; p++)
            #pragma unroll
            for (int j = 0; j < 4; j++) acc[p][j] = 0ull;
        {
            const float4* pt = (const float4*)(PiT_s + 4 * l);
            #pragma unroll 8
            for (int k = 0; k < D; k++) {
                float4 pv = pt[k * (D / 4)];
                unsigned long long s0 = splat2(pv.x), s1 = splat2(pv.y),
                                   s2 = splat2(pv.z), s3 = splat2(pv.w);
                #pragma unroll
                for (int p = 0; p < 4; p++) {
                    unsigned long long xv = Xs[(pgbase + p) * PAIR_PAD + k];
                    fma2(acc[p][0], xv, s0);
                    fma2(acc[p][1], xv, s1);
                    fma2(acc[p][2], xv, s2);
                    fma2(acc[p][3], xv, s3);
                }
            }
        }

        // ---------------- quantize: scale by inv-norm, binary-search bucketize ----------------
        #pragma unroll
        for (int p = 0; p < 4; p++) {
            int pg = pgbase + p;
            float ia = inv2[pg * 2 + 0];
            float ib = inv2[pg * 2 + 1];
            #pragma unroll
            for (int jj = 0; jj < 4; jj++) {
                float2 r2 = unpack2(acc[p][jj]);
                float va = r2.x * ia;
                float vb = r2.y * ib;
                int ida = (va > sI[7]) ? 8 : 0;
                ida += (va > sI[ida + 3]) ? 4 : 0;
                ida += (va > sI[ida + 1]) ? 2 : 0;
                ida += (va > sI[ida + 0]) ? 1 : 0;
                int idb = (vb > sI[7]) ? 8 : 0;
                idb += (vb > sI[idb + 3]) ? 4 : 0;
                idb += (vb > sI[idb + 1]) ? 2 : 0;
                idb += (vb > sI[idb + 0]) ? 1 : 0;
                Vs[pg * PAIR_PAD + 4 * l + jj] = pack2(sC[ida], sC[idb]);
            }
        }
        __syncwarp();

        // ---------------- GEMM2: O[m,k] = sum_j V[m,j] * Pi[j,k]  (Pi in smem) ----------------
        unsigned long long acc2[4][4];
        #pragma unroll
        for (int p = 0; p < 4; p++)
            #pragma unroll
            for (int j = 0; j < 4; j++) acc2[p][j] = 0ull;
        {
            const float4* pr = (const float4*)(Pi_s + 4 * l);
            #pragma unroll 8
            for (int j = 0; j < D; j++) {
                float4 pv = pr[j * (D / 4)];
                unsigned long long s0 = splat2(pv.x), s1 = splat2(pv.y),
                                   s2 = splat2(pv.z), s3 = splat2(pv.w);
                #pragma unroll
                for (int p = 0; p < 4; p++) {
                    unsigned long long vv = Vs[(pgbase + p) * PAIR_PAD + j];
                    fma2(acc2[p][0], vv, s0);
                    fma2(acc2[p][1], vv, s1);
                    fma2(acc2[p][2], vv, s2);
                    fma2(acc2[p][3], vv, s3);
                }
            }
        }

        // ---------------- epilogue: rescale by fp16-roundtrip norm, coalesced STG.128 ----------------
        #pragma unroll
        for (int p = 0; p < 4; p++) {
            int pg = pgbase + p;
            float na = nq2[pg * 2 + 0];
            float nb = nq2[pg * 2 + 1];
            float2 c0 = unpack2(acc2[p][0]);
            float2 c1 = unpack2(acc2[p][1]);
            float2 c2 = unpack2(acc2[p][2]);
            float2 c3 = unpack2(acc2[p][3]);
            int rowA = row0 + pg * 2;
            int rowB = rowA + 1;
            if (rowA < nrows) {
                float4 oa = make_float4(c0.x * na, c1.x * na, c2.x * na, c3.x * na);
                *(float4*)(out + (size_t)rowA * D + 4 * l) = oa;
            }
            if (rowB < nrows) {
                float4 ob = make_float4(c0.y * nb, c1.y * nb, c2.y * nb, c3.y * nb);
                *(float4*)(out + (size_t)rowB * D + 4 * l) = ob;
            }
        }
        __syncwarp();  // protect Xs/Vs/norms against next iteration's staging
    }
}

extern "C" void kernel_launch(void* const* d_in, const int* in_sizes, int n_in,
                              void* d_out, int out_size) {
    const float* x    = (const float*)d_in[0];
    const float* Pi   = (const float*)d_in[1];
    const float* cent = (const float*)d_in[2];
    const float* bnd  = (const float*)d_in[3];
    float* out = (float*)d_out;

    int nrows  = in_sizes[0] / D;
    int ntiles = (nrows + TILE_ROWS - 1) / TILE_ROWS;

    cudaFuncSetAttribute(tq_kernel, cudaFuncAttributeMaxDynamicSharedMemorySize,
                         SMEM_BYTES);

    int grid = ntiles < 592 ? ntiles : 592;  // persistent-ish, 1 CTA/SM residency
    tq_kernel<<<grid, NTHREADS, SMEM_BYTES>>>(x, Pi, cent, bnd, out, nrows, ntiles);
}

// round 3
// speedup vs baseline: 1.0590x; 1.0590x over previous
#include <cuda_runtime.h>
#include <cuda_fp16.h>

#define D 128
#define PJ 129            /* Pi smem row stride (floats, odd => conflict-free strided-lane access) */
#define TILE_ROWS 128
#define TILE_PAIRS 64
#define XS_STRIDE 130     /* ull stride per pair row (even for 16B align, breaks staging conflicts) */
#define NTHREADS 256
#define P_W 8             /* row-pairs per warp */

#define SMEM_BYTES (66048 /*Pi*/ + 66560 /*Xs*/ + 66560 /*Vs*/ + 512 + 512 + 64 + 64)

// ---- packed f32x2 helpers (sm_103a FFMA2 path) ----
__device__ __forceinline__ unsigned long long splat2(float v) {
    unsigned long long r;
    asm("mov.b64 %0, {%1, %1};" : "=l"(r) : "f"(v));
    return r;
}
__device__ __forceinline__ void fma2(unsigned long long &d, unsigned long long a,
                                     unsigned long long b) {
    asm("fma.rn.f32x2 %0, %1, %2, %0;" : "+l"(d) : "l"(a), "l"(b));
}
__device__ __forceinline__ float2 unpack2(unsigned long long v) {
    float2 f;
    asm("mov.b64 {%0, %1}, %2;" : "=f"(f.x), "=f"(f.y) : "l"(v));
    return f;
}
__device__ __forceinline__ unsigned long long pack2(float x, float y) {
    unsigned long long r;
    asm("mov.b64 %0, {%1, %2};" : "=l"(r) : "f"(x), "f"(y));
    return r;
}

extern "C" __global__ void __launch_bounds__(NTHREADS, 1)
tq_kernel(const float* __restrict__ x, const float* __restrict__ Pi,
          const float* __restrict__ cent, const float* __restrict__ bnd,
          float* __restrict__ out, int nrows, int ntiles)
{
    extern __shared__ char smem[];
    float* Pi_s = (float*)smem;                                       // [128][129]
    unsigned long long* Xs = (unsigned long long*)(smem + 66048);     // [64][130] pairs
    unsigned long long* Vs = Xs + TILE_PAIRS * XS_STRIDE;             // [64][130] pairs
    float* inv2 = (float*)(Vs + TILE_PAIRS * XS_STRIDE);              // [128] 1/(norm+eps)
    float* nq2  = inv2 + 128;                                         // [128] fp16-roundtrip norm
    float* sI   = nq2 + 128;                                          // [15] interior boundaries
    float* sC   = sI + 16;                                            // [16] centroids

    const int t = threadIdx.x;
    const int w = t >> 5;
    const int l = t & 31;

    // ---------- one-time setup: tables + Pi staging (row-major, stride PJ) ----------
    if (t < 16) sC[t] = cent[t];
    if (t < 15) sI[t] = bnd[t + 1];
    {
        int j  = t >> 1;
        int k0 = (t & 1) * 64;
        const float4* src = (const float4*)(Pi + j * D + k0);
        float* dst = Pi_s + j * PJ + k0;
        #pragma unroll
        for (int i = 0; i < 16; i++) {
            float4 v = src[i];
            dst[4 * i + 0] = v.x; dst[4 * i + 1] = v.y;
            dst[4 * i + 2] = v.z; dst[4 * i + 3] = v.w;
        }
    }
    __syncthreads();

    const int pg0    = w * P_W;         // this warp's 8 row-pairs
    const int r_loc  = t >> 1;          // staging: row in tile (0..127)
    const int khalf  = (t & 1) * 64;    // staging: k half
    const int pg_st  = r_loc >> 1;
    const int half   = r_loc & 1;

    for (int tile = blockIdx.x; tile < ntiles; tile += gridDim.x) {
        const int row0 = tile * TILE_ROWS;

        // ---------- stage X tile (pair-interleaved ull layout) + row norms ----------
        {
            int row = row0 + r_loc;
            float s = 0.f;
            float* dstf = (float*)Xs;   // word index = (pair*XS_STRIDE + k)*2 + half
            if (row < nrows) {
                const float4* xr = (const float4*)(x + (size_t)row * D + khalf);
                #pragma unroll
                for (int i = 0; i < 16; i++) {
                    float4 v = xr[i];
                    s += v.x * v.x + v.y * v.y + v.z * v.z + v.w * v.w;
                    int base = ((pg_st * XS_STRIDE + khalf + 4 * i) << 1) + half;
                    dstf[base + 0] = v.x; dstf[base + 2] = v.y;
                    dstf[base + 4] = v.z; dstf[base + 6] = v.w;
                }
            } else {
                #pragma unroll
                for (int i = 0; i < 16; i++) {
                    int base = ((pg_st * XS_STRIDE + khalf + 4 * i) << 1) + half;
                    dstf[base + 0] = 0.f; dstf[base + 2] = 0.f;
                    dstf[base + 4] = 0.f; dstf[base + 6] = 0.f;
                }
            }
            s += __shfl_xor_sync(0xffffffffu, s, 1);
            if ((t & 1) == 0) {
                float norm = sqrtf(s);
                inv2[r_loc] = 1.0f / (norm + 1e-8f);
                nq2[r_loc]  = __half2float(__float2half_rn(norm));
            }
        }
        __syncwarp();

        // ---------- GEMM1: R[pair][j] = sum_k X[pair][k] * Pi[j][k],  j = l + 32*jj ----------
        unsigned long long acc[P_W][4];
        #pragma unroll
        for (int p = 0; p < P_W; p++)
            #pragma unroll
            for (int jj = 0; jj < 4; jj++) acc[p][jj] = 0ull;
        {
            const float* pr0 = Pi_s + (l +  0) * PJ;
            const float* pr1 = Pi_s + (l + 32) * PJ;
            const float* pr2 = Pi_s + (l + 64) * PJ;
            const float* pr3 = Pi_s + (l + 96) * PJ;
            #pragma unroll 2
            for (int k = 0; k < D; k += 2) {
                unsigned long long s00 = splat2(pr0[k]), s01 = splat2(pr0[k + 1]);
                unsigned long long s10 = splat2(pr1[k]), s11 = splat2(pr1[k + 1]);
                unsigned long long s20 = splat2(pr2[k]), s21 = splat2(pr2[k + 1]);
                unsigned long long s30 = splat2(pr3[k]), s31 = splat2(pr3[k + 1]);
                #pragma unroll
                for (int p = 0; p < P_W; p++) {
                    ulonglong2 xv = *(const ulonglong2*)(Xs + (pg0 + p) * XS_STRIDE + k);
                    fma2(acc[p][0], xv.x, s00); fma2(acc[p][0], xv.y, s01);
                    fma2(acc[p][1], xv.x, s10); fma2(acc[p][1], xv.y, s11);
                    fma2(acc[p][2], xv.x, s20); fma2(acc[p][2], xv.y, s21);
                    fma2(acc[p][3], xv.x, s30); fma2(acc[p][3], xv.y, s31);
                }
            }
        }

        // ---------- quantize: scale by inv-norm, 4-level binary search, centroid gather ----------
        #pragma unroll
        for (int p = 0; p < P_W; p++) {
            int pg = pg0 + p;
            float ia = inv2[pg * 2 + 0];
            float ib = inv2[pg * 2 + 1];
            #pragma unroll
            for (int jj = 0; jj < 4; jj++) {
                float2 r2 = unpack2(acc[p][jj]);
                float va = r2.x * ia;
                float vb = r2.y * ib;
                int ida = (va > sI[7]) ? 8 : 0;
                ida += (va > sI[ida + 3]) ? 4 : 0;
                ida += (va > sI[ida + 1]) ? 2 : 0;
                ida += (va > sI[ida + 0]) ? 1 : 0;
                int idb = (vb > sI[7]) ? 8 : 0;
                idb += (vb > sI[idb + 3]) ? 4 : 0;
                idb += (vb > sI[idb + 1]) ? 2 : 0;
                idb += (vb > sI[idb + 0]) ? 1 : 0;
                Vs[pg * XS_STRIDE + l + 32 * jj] = pack2(sC[ida], sC[idb]);
            }
        }
        __syncwarp();

        // ---------- GEMM2: O[pair][k] = sum_j V[pair][j] * Pi[j][k],  k = l + 32*kk ----------
        unsigned long long acc2[P_W][4];
        #pragma unroll
        for (int p = 0; p < P_W; p++)
            #pragma unroll
            for (int kk = 0; kk < 4; kk++) acc2[p][kk] = 0ull;
        {
            #pragma unroll 2
            for (int j = 0; j < D; j += 2) {
                const float* pa = Pi_s + j * PJ + l;
                const float* pb = pa + PJ;
                unsigned long long t00 = splat2(pa[0]),  t01 = splat2(pb[0]);
                unsigned long long t10 = splat2(pa[32]), t11 = splat2(pb[32]);
                unsigned long long t20 = splat2(pa[64]), t21 = splat2(pb[64]);
                unsigned long long t30 = splat2(pa[96]), t31 = splat2(pb[96]);
                #pragma unroll
                for (int p = 0; p < P_W; p++) {
                    ulonglong2 vv = *(const ulonglong2*)(Vs + (pg0 + p) * XS_STRIDE + j);
                    fma2(acc2[p][0], vv.x, t00); fma2(acc2[p][0], vv.y, t01);
                    fma2(acc2[p][1], vv.x, t10); fma2(acc2[p][1], vv.y, t11);
                    fma2(acc2[p][2], vv.x, t20); fma2(acc2[p][2], vv.y, t21);
                    fma2(acc2[p][3], vv.x, t30); fma2(acc2[p][3], vv.y, t31);
                }
            }
        }

        // ---------- epilogue: rescale by fp16-roundtrip norm, coalesced STG.32 ----------
        #pragma unroll
        for (int p = 0; p < P_W; p++) {
            int pg = pg0 + p;
            float na = nq2[pg * 2 + 0];
            float nb = nq2[pg * 2 + 1];
            int rowA = row0 + pg * 2;
            int rowB = rowA + 1;
            float* oA = out + (size_t)rowA * D + l;
            float* oB = out + (size_t)rowB * D + l;
            #pragma unroll
            for (int kk = 0; kk < 4; kk++) {
                float2 c = unpack2(acc2[p][kk]);
                if (rowA < nrows) oA[32 * kk] = c.x * na;
                if (rowB < nrows) oB[32 * kk] = c.y * nb;
            }
        }
        __syncwarp();  // protect Xs/Vs/norms against next iteration's staging
    }
}

extern "C" void kernel_launch(void* const* d_in, const int* in_sizes, int n_in,
                              void* d_out, int out_size) {
    const float* x    = (const float*)d_in[0];
    const float* Pi   = (const float*)d_in[1];
    const float* cent = (const float*)d_in[2];
    const float* bnd  = (const float*)d_in[3];
    float* out = (float*)d_out;

    int nrows  = in_sizes[0] / D;
    int ntiles = (nrows + TILE_ROWS - 1) / TILE_ROWS;

    cudaFuncSetAttribute(tq_kernel, cudaFuncAttributeMaxDynamicSharedMemorySize,
                         SMEM_BYTES);

    int grid = ntiles < 148 ? ntiles : 148;  // persistent: 1 CTA/SM, Pi staged once
    tq_kernel<<<grid, NTHREADS, SMEM_BYTES>>>(x, Pi, cent, bnd, out, nrows, ntiles);
}

// round 5
// speedup vs baseline: 1.0608x; 1.0017x over previous
#include <cuda_runtime.h>
#include <cuda_fp16.h>

#define D 128
#define PJ 129            /* Pi smem row stride (floats, odd => conflict-free strided-lane access) */
#define TILE_ROWS 128
#define TILE_PAIRS 64
#define XS_STRIDE 130     /* ull stride per pair row (even for 16B align, breaks staging conflicts) */
#define NTHREADS 256
#define P_W 8             /* row-pairs per warp */

#define SMEM_BYTES (66048 /*Pi*/ + 66560 /*Xs*/ + 66560 /*Vs*/ + 512 + 512 + 64 + 64)

// ---- packed f32x2 helpers (sm_103a FFMA2 path) ----
__device__ __forceinline__ unsigned long long splat2(float v) {
    unsigned long long r;
    asm("mov.b64 %0, {%1, %1};" : "=l"(r) : "f"(v));
    return r;
}
__device__ __forceinline__ void fma2(unsigned long long &d, unsigned long long a,
                                     unsigned long long b) {
    asm("fma.rn.f32x2 %0, %1, %2, %0;" : "+l"(d) : "l"(a), "l"(b));
}
__device__ __forceinline__ float2 unpack2(unsigned long long v) {
    float2 f;
    asm("mov.b64 {%0, %1}, %2;" : "=f"(f.x), "=f"(f.y) : "l"(v));
    return f;
}
__device__ __forceinline__ unsigned long long pack2(float x, float y) {
    unsigned long long r;
    asm("mov.b64 %0, {%1, %2};" : "=l"(r) : "f"(x), "f"(y));
    return r;
}

extern "C" __global__ void __launch_bounds__(NTHREADS, 1)
tq_kernel(const float* __restrict__ x, const float* __restrict__ Pi,
          const float* __restrict__ cent, const float* __restrict__ bnd,
          float* __restrict__ out, int nrows, int ntiles)
{
    extern __shared__ char smem[];
    float* Pi_s = (float*)smem;                                       // [128][129]
    unsigned long long* Xs = (unsigned long long*)(smem + 66048);     // [64][130] pairs
    unsigned long long* Vs = Xs + TILE_PAIRS * XS_STRIDE;             // [64][130] pairs
    float* inv2 = (float*)(Vs + TILE_PAIRS * XS_STRIDE);              // [128] 1/(norm+eps)
    float* nq2  = inv2 + 128;                                         // [128] fp16-roundtrip norm
    float* sI   = nq2 + 128;                                          // [15] interior boundaries
    float* sC   = sI + 16;                                            // [16] centroids

    const int t = threadIdx.x;
    const int w = t >> 5;
    const int l = t & 31;

    // ---------- one-time setup: tables + Pi staging (row-major, stride PJ) ----------
    if (t < 16) sC[t] = cent[t];
    if (t < 15) sI[t] = bnd[t + 1];
    {
        int j  = t >> 1;
        int k0 = (t & 1) * 64;
        const float4* src = (const float4*)(Pi + j * D + k0);
        float* dst = Pi_s + j * PJ + k0;
        #pragma unroll
        for (int i = 0; i < 16; i++) {
            float4 v = src[i];
            dst[4 * i + 0] = v.x; dst[4 * i + 1] = v.y;
            dst[4 * i + 2] = v.z; dst[4 * i + 3] = v.w;
        }
    }
    __syncthreads();

    const int pg0    = w * P_W;         // this warp's 8 row-pairs
    const int r_loc  = t >> 1;          // staging: row in tile (0..127)
    const int khalf  = (t & 1) * 64;    // staging: k half
    const int pg_st  = r_loc >> 1;
    const int half   = r_loc & 1;

    for (int tile = blockIdx.x; tile < ntiles; tile += gridDim.x) {
        const int row0 = tile * TILE_ROWS;

        // ---------- stage X tile (pair-interleaved ull layout) + row norms ----------
        {
            int row = row0 + r_loc;
            float s = 0.f;
            float* dstf = (float*)Xs;   // word index = (pair*XS_STRIDE + k)*2 + half
            if (row < nrows) {
                const float4* xr = (const float4*)(x + (size_t)row * D + khalf);
                #pragma unroll
                for (int i = 0; i < 16; i++) {
                    float4 v = xr[i];
                    s += v.x * v.x + v.y * v.y + v.z * v.z + v.w * v.w;
                    int base = ((pg_st * XS_STRIDE + khalf + 4 * i) << 1) + half;
                    dstf[base + 0] = v.x; dstf[base + 2] = v.y;
                    dstf[base + 4] = v.z; dstf[base + 6] = v.w;
                }
            } else {
                #pragma unroll
                for (int i = 0; i < 16; i++) {
                    int base = ((pg_st * XS_STRIDE + khalf + 4 * i) << 1) + half;
                    dstf[base + 0] = 0.f; dstf[base + 2] = 0.f;
                    dstf[base + 4] = 0.f; dstf[base + 6] = 0.f;
                }
            }
            s += __shfl_xor_sync(0xffffffffu, s, 1);
            if ((t & 1) == 0) {
                float norm = sqrtf(s);
                inv2[r_loc] = 1.0f / (norm + 1e-8f);
                nq2[r_loc]  = __half2float(__float2half_rn(norm));
            }
        }
        __syncwarp();

        // ---------- GEMM1: R[pair][j] = sum_k X[pair][k] * Pi[j][k],  j = l + 32*jj ----------
        unsigned long long acc[P_W][4];
        #pragma unroll
        for (int p = 0; p < P_W; p++)
            #pragma unroll
            for (int jj = 0; jj < 4; jj++) acc[p][jj] = 0ull;
        {
            const float* pr0 = Pi_s + (l +  0) * PJ;
            const float* pr1 = Pi_s + (l + 32) * PJ;
            const float* pr2 = Pi_s + (l + 64) * PJ;
            const float* pr3 = Pi_s + (l + 96) * PJ;
            #pragma unroll 2
            for (int k = 0; k < D; k += 2) {
                unsigned long long s00 = splat2(pr0[k]), s01 = splat2(pr0[k + 1]);
                unsigned long long s10 = splat2(pr1[k]), s11 = splat2(pr1[k + 1]);
                unsigned long long s20 = splat2(pr2[k]), s21 = splat2(pr2[k + 1]);
                unsigned long long s30 = splat2(pr3[k]), s31 = splat2(pr3[k + 1]);
                #pragma unroll
                for (int p = 0; p < P_W; p++) {
                    ulonglong2 xv = *(const ulonglong2*)(Xs + (pg0 + p) * XS_STRIDE + k);
                    fma2(acc[p][0], xv.x, s00); fma2(acc[p][0], xv.y, s01);
                    fma2(acc[p][1], xv.x, s10); fma2(acc[p][1], xv.y, s11);
                    fma2(acc[p][2], xv.x, s20); fma2(acc[p][2], xv.y, s21);
                    fma2(acc[p][3], xv.x, s30); fma2(acc[p][3], xv.y, s31);
                }
            }
        }

        // ---------- quantize: scale by inv-norm, 4-level binary search, centroid gather ----------
        #pragma unroll
        for (int p = 0; p < P_W; p++) {
            int pg = pg0 + p;
            float ia = inv2[pg * 2 + 0];
            float ib = inv2[pg * 2 + 1];
            #pragma unroll
            for (int jj = 0; jj < 4; jj++) {
                float2 r2 = unpack2(acc[p][jj]);
                float va = r2.x * ia;
                float vb = r2.y * ib;
                int ida = (va > sI[7]) ? 8 : 0;
                ida += (va > sI[ida + 3]) ? 4 : 0;
                ida += (va > sI[ida + 1]) ? 2 : 0;
                ida += (va > sI[ida + 0]) ? 1 : 0;
                int idb = (vb > sI[7]) ? 8 : 0;
                idb += (vb > sI[idb + 3]) ? 4 : 0;
                idb += (vb > sI[idb + 1]) ? 2 : 0;
                idb += (vb > sI[idb + 0]) ? 1 : 0;
                Vs[pg * XS_STRIDE + l + 32 * jj] = pack2(sC[ida], sC[idb]);
            }
        }
        __syncwarp();

        // ---------- GEMM2: O[pair][k] = sum_j V[pair][j] * Pi[j][k],  k = l + 32*kk ----------
        unsigned long long acc2[P_W][4];
        #pragma unroll
        for (int p = 0; p < P_W; p++)
            #pragma unroll
            for (int kk = 0; kk < 4; kk++) acc2[p][kk] = 0ull;
        {
            #pragma unroll 2
            for (int j = 0; j < D; j += 2) {
                const float* pa = Pi_s + j * PJ + l;
                const float* pb = pa + PJ;
                unsigned long long t00 = splat2(pa[0]),  t01 = splat2(pb[0]);
                unsigned long long t10 = splat2(pa[32]), t11 = splat2(pb[32]);
                unsigned long long t20 = splat2(pa[64]), t21 = splat2(pb[64]);
                unsigned long long t30 = splat2(pa[96]), t31 = splat2(pb[96]);
                #pragma unroll
                for (int p = 0; p < P_W; p++) {
                    ulonglong2 vv = *(const ulonglong2*)(Vs + (pg0 + p) * XS_STRIDE + j);
                    fma2(acc2[p][0], vv.x, t00); fma2(acc2[p][0], vv.y, t01);
                    fma2(acc2[p][1], vv.x, t10); fma2(acc2[p][1], vv.y, t11);
                    fma2(acc2[p][2], vv.x, t20); fma2(acc2[p][2], vv.y, t21);
                    fma2(acc2[p][3], vv.x, t30); fma2(acc2[p][3], vv.y, t31);
                }
            }
        }

        // ---------- epilogue: rescale by fp16-roundtrip norm, coalesced STG.32 ----------
        #pragma unroll
        for (int p = 0; p < P_W; p++) {
            int pg = pg0 + p;
            float na = nq2[pg * 2 + 0];
            float nb = nq2[pg * 2 + 1];
            int rowA = row0 + pg * 2;
            int rowB = rowA + 1;
            float* oA = out + (size_t)rowA * D + l;
            float* oB = out + (size_t)rowB * D + l;
            #pragma unroll
            for (int kk = 0; kk < 4; kk++) {
                float2 c = unpack2(acc2[p][kk]);
                if (rowA < nrows) oA[32 * kk] = c.x * na;
                if (rowB < nrows) oB[32 * kk] = c.y * nb;
            }
        }
        __syncwarp();  // protect Xs/Vs/norms against next iteration's staging
    }
}

extern "C" void kernel_launch(void* const* d_in, const int* in_sizes, int n_in,
                              void* d_out, int out_size) {
    const float* x    = (const float*)d_in[0];
    const float* Pi   = (const float*)d_in[1];
    const float* cent = (const float*)d_in[2];
    const float* bnd  = (const float*)d_in[3];
    float* out = (float*)d_out;

    int nrows  = in_sizes[0] / D;
    int ntiles = (nrows + TILE_ROWS - 1) / TILE_ROWS;

    cudaFuncSetAttribute(tq_kernel, cudaFuncAttributeMaxDynamicSharedMemorySize,
                         SMEM_BYTES);

    int grid = ntiles < 148 ? ntiles : 148;  // persistent: 1 CTA/SM, Pi staged once
    tq_kernel<<<grid, NTHREADS, SMEM_BYTES>>>(x, Pi, cent, bnd, out, nrows, ntiles);
}

// round 6
// speedup vs baseline: 1.0699x; 1.0085x over previous
#include <cuda_runtime.h>
#include <cuda_fp16.h>

#define D 128
#define PJ 129            /* Pi smem row stride (floats, odd => conflict-free strided-lane access) */
#define TILE_ROWS 256
#define TILE_PAIRS 128
#define XS_STRIDE 130     /* ull stride per pair row (even for 16B align) */
#define NTHREADS 512
#define NWARPS 16
#define P_W 8             /* row-pairs per warp */

/* Pi 66048 + Xs(=Vs, in-place) 133120 + inv2 1024 + nq2 1024 + tables 128 */
#define SMEM_BYTES (66048 + 133120 + 1024 + 1024 + 64 + 64)

// ---- packed f32x2 helpers (sm_103a FFMA2 path) ----
__device__ __forceinline__ unsigned long long splat2(float v) {
    unsigned long long r;
    asm("mov.b64 %0, {%1, %1};" : "=l"(r) : "f"(v));
    return r;
}
__device__ __forceinline__ void fma2(unsigned long long &d, unsigned long long a,
                                     unsigned long long b) {
    asm("fma.rn.f32x2 %0, %1, %2, %0;" : "+l"(d) : "l"(a), "l"(b));
}
__device__ __forceinline__ float2 unpack2(unsigned long long v) {
    float2 f;
    asm("mov.b64 {%0, %1}, %2;" : "=f"(f.x), "=f"(f.y) : "l"(v));
    return f;
}
__device__ __forceinline__ unsigned long long pack2(float x, float y) {
    unsigned long long r;
    asm("mov.b64 %0, {%1, %2};" : "=l"(r) : "f"(x), "f"(y));
    return r;
}

extern "C" __global__ void __launch_bounds__(NTHREADS, 1)
tq_kernel(const float* __restrict__ x, const float* __restrict__ Pi,
          const float* __restrict__ cent, const float* __restrict__ bnd,
          float* __restrict__ out, int nrows, int ntiles)
{
    extern __shared__ char smem[];
    float* Pi_s = (float*)smem;                                       // [128][129]
    unsigned long long* Xs = (unsigned long long*)(smem + 66048);     // [128][130] pairs
    unsigned long long* Vs = Xs;                                      // in-place: warp-local rows
    float* inv2 = (float*)(smem + 66048 + 133120);                    // [256] 1/(norm+eps)
    float* nq2  = inv2 + 256;                                         // [256] fp16-roundtrip norm
    float* sI   = nq2 + 256;                                          // [15] interior boundaries
    float* sC   = sI + 16;                                            // [16] centroids

    const int t = threadIdx.x;
    const int w = t >> 5;
    const int l = t & 31;

    // ---------- one-time setup: tables + Pi staging (row-major, stride PJ) ----------
    if (t < 16) sC[t] = cent[t];
    if (t < 15) sI[t] = bnd[t + 1];
    {
        int j  = t >> 2;           // 0..127
        int k0 = (t & 3) * 32;     // quarter-row
        const float4* src = (const float4*)(Pi + j * D + k0);
        float* dst = Pi_s + j * PJ + k0;
        #pragma unroll
        for (int i = 0; i < 8; i++) {
            float4 v = src[i];
            dst[4 * i + 0] = v.x; dst[4 * i + 1] = v.y;
            dst[4 * i + 2] = v.z; dst[4 * i + 3] = v.w;
        }
    }
    __syncthreads();

    const int pg0    = w * P_W;         // this warp's 8 row-pairs
    const int r_loc  = t >> 1;          // staging: row in tile (0..255); warp-local: rows 16w..16w+15
    const int khalf  = (t & 1) * 64;    // staging: k half
    const int pg_st  = r_loc >> 1;
    const int half   = r_loc & 1;

    for (int tile = blockIdx.x; tile < ntiles; tile += gridDim.x) {
        const int row0 = tile * TILE_ROWS;

        // ---------- stage X tile (pair-interleaved ull layout) + row norms ----------
        {
            int row = row0 + r_loc;
            float s = 0.f;
            float* dstf = (float*)Xs;   // word index = (pair*XS_STRIDE + k)*2 + half
            if (row < nrows) {
                const float4* xr = (const float4*)(x + (size_t)row * D + khalf);
                #pragma unroll
                for (int i = 0; i < 16; i++) {
                    float4 v = xr[i];
                    s += v.x * v.x + v.y * v.y + v.z * v.z + v.w * v.w;
                    int base = ((pg_st * XS_STRIDE + khalf + 4 * i) << 1) + half;
                    dstf[base + 0] = v.x; dstf[base + 2] = v.y;
                    dstf[base + 4] = v.z; dstf[base + 6] = v.w;
                }
            } else {
                #pragma unroll
                for (int i = 0; i < 16; i++) {
                    int base = ((pg_st * XS_STRIDE + khalf + 4 * i) << 1) + half;
                    dstf[base + 0] = 0.f; dstf[base + 2] = 0.f;
                    dstf[base + 4] = 0.f; dstf[base + 6] = 0.f;
                }
            }
            s += __shfl_xor_sync(0xffffffffu, s, 1);
            if ((t & 1) == 0) {
                float norm = sqrtf(s);
                inv2[r_loc] = 1.0f / (norm + 1e-8f);
                nq2[r_loc]  = __half2float(__float2half_rn(norm));
            }
        }
        __syncwarp();

        // ---------- GEMM1: R[pair][j] = sum_k X[pair][k] * Pi[j][k],  j = l + 32*jj ----------
        unsigned long long acc[P_W][4];
        #pragma unroll
        for (int p = 0; p < P_W; p++)
            #pragma unroll
            for (int jj = 0; jj < 4; jj++) acc[p][jj] = 0ull;
        {
            const float* pr0 = Pi_s + (l +  0) * PJ;
            const float* pr1 = Pi_s + (l + 32) * PJ;
            const float* pr2 = Pi_s + (l + 64) * PJ;
            const float* pr3 = Pi_s + (l + 96) * PJ;
            #pragma unroll 2
            for (int k = 0; k < D; k += 2) {
                unsigned long long s00 = splat2(pr0[k]), s01 = splat2(pr0[k + 1]);
                unsigned long long s10 = splat2(pr1[k]), s11 = splat2(pr1[k + 1]);
                unsigned long long s20 = splat2(pr2[k]), s21 = splat2(pr2[k + 1]);
                unsigned long long s30 = splat2(pr3[k]), s31 = splat2(pr3[k + 1]);
                #pragma unroll
                for (int p = 0; p < P_W; p++) {
                    ulonglong2 xv = *(const ulonglong2*)(Xs + (pg0 + p) * XS_STRIDE + k);
                    fma2(acc[p][0], xv.x, s00); fma2(acc[p][0], xv.y, s01);
                    fma2(acc[p][1], xv.x, s10); fma2(acc[p][1], xv.y, s11);
                    fma2(acc[p][2], xv.x, s20); fma2(acc[p][2], xv.y, s21);
                    fma2(acc[p][3], xv.x, s30); fma2(acc[p][3], xv.y, s31);
                }
            }
        }
        __syncwarp();   // all GEMM1 reads of this warp's Xs rows complete before overwrite

        // ---------- quantize: scale by inv-norm, 4-level binary search; write V IN-PLACE ----------
        #pragma unroll
        for (int p = 0; p < P_W; p++) {
            int pg = pg0 + p;
            float ia = inv2[pg * 2 + 0];
            float ib = inv2[pg * 2 + 1];
            #pragma unroll
            for (int jj = 0; jj < 4; jj++) {
                float2 r2 = unpack2(acc[p][jj]);
                float va = r2.x * ia;
                float vb = r2.y * ib;
                int ida = (va > sI[7]) ? 8 : 0;
                ida += (va > sI[ida + 3]) ? 4 : 0;
                ida += (va > sI[ida + 1]) ? 2 : 0;
                ida += (va > sI[ida + 0]) ? 1 : 0;
                int idb = (vb > sI[7]) ? 8 : 0;
                idb += (vb > sI[idb + 3]) ? 4 : 0;
                idb += (vb > sI[idb + 1]) ? 2 : 0;
                idb += (vb > sI[idb + 0]) ? 1 : 0;
                Vs[pg * XS_STRIDE + l + 32 * jj] = pack2(sC[ida], sC[idb]);
            }
        }
        __syncwarp();

        // ---------- GEMM2: O[pair][k] = sum_j V[pair][j] * Pi[j][k],  k = l + 32*kk ----------
        unsigned long long acc2[P_W][4];
        #pragma unroll
        for (int p = 0; p < P_W; p++)
            #pragma unroll
            for (int kk = 0; kk < 4; kk++) acc2[p][kk] = 0ull;
        {
            #pragma unroll 2
            for (int j = 0; j < D; j += 2) {
                const float* pa = Pi_s + j * PJ + l;
                const float* pb = pa + PJ;
                unsigned long long t00 = splat2(pa[0]),  t01 = splat2(pb[0]);
                unsigned long long t10 = splat2(pa[32]), t11 = splat2(pb[32]);
                unsigned long long t20 = splat2(pa[64]), t21 = splat2(pb[64]);
                unsigned long long t30 = splat2(pa[96]), t31 = splat2(pb[96]);
                #pragma unroll
                for (int p = 0; p < P_W; p++) {
                    ulonglong2 vv = *(const ulonglong2*)(Vs + (pg0 + p) * XS_STRIDE + j);
                    fma2(acc2[p][0], vv.x, t00); fma2(acc2[p][0], vv.y, t01);
                    fma2(acc2[p][1], vv.x, t10); fma2(acc2[p][1], vv.y, t11);
                    fma2(acc2[p][2], vv.x, t20); fma2(acc2[p][2], vv.y, t21);
                    fma2(acc2[p][3], vv.x, t30); fma2(acc2[p][3], vv.y, t31);
                }
            }
        }

        // ---------- epilogue: rescale by fp16-roundtrip norm, coalesced STG.32 ----------
        #pragma unroll
        for (int p = 0; p < P_W; p++) {
            int pg = pg0 + p;
            float na = nq2[pg * 2 + 0];
            float nb = nq2[pg * 2 + 1];
            int rowA = row0 + pg * 2;
            int rowB = rowA + 1;
            float* oA = out + (size_t)rowA * D + l;
            float* oB = out + (size_t)rowB * D + l;
            #pragma unroll
            for (int kk = 0; kk < 4; kk++) {
                float2 c = unpack2(acc2[p][kk]);
                if (rowA < nrows) oA[32 * kk] = c.x * na;
                if (rowB < nrows) oB[32 * kk] = c.y * nb;
            }
        }
        __syncwarp();  // protect Xs/norms against next iteration's staging
    }
}

extern "C" void kernel_launch(void* const* d_in, const int* in_sizes, int n_in,
                              void* d_out, int out_size) {
    const float* x    = (const float*)d_in[0];
    const float* Pi   = (const float*)d_in[1];
    const float* cent = (const float*)d_in[2];
    const float* bnd  = (const float*)d_in[3];
    float* out = (float*)d_out;

    int nrows  = in_sizes[0] / D;
    int ntiles = (nrows + TILE_ROWS - 1) / TILE_ROWS;

    cudaFuncSetAttribute(tq_kernel, cudaFuncAttributeMaxDynamicSharedMemorySize,
                         SMEM_BYTES);

    int grid = ntiles < 148 ? ntiles : 148;  // persistent: 1 CTA/SM, Pi staged once
    tq_kernel<<<grid, NTHREADS, SMEM_BYTES>>>(x, Pi, cent, bnd, out, nrows, ntiles);
}

// round 7
// speedup vs baseline: 1.1302x; 1.0564x over previous
#include <cuda_runtime.h>
#include <cuda_fp16.h>

#define D 128
#define PJ 129            /* Pi smem row stride (floats, odd => conflict-free strided-lane access) */
#define TILE_ROWS 256
#define TILE_PAIRS 128
#define XS_STRIDE 130     /* ull stride per pair row (even for 16B align) */
#define NTHREADS 512
#define NWARPS 16
#define P_W 8             /* row-pairs per warp */

/* Pi 66048 + Xs(=Vs, in-place) 133120 + inv2 1024 + nq2 1024 + tables 128 */
#define SMEM_BYTES (66048 + 133120 + 1024 + 1024 + 64 + 64)

// ---- packed f32x2 helpers (sm_103a FFMA2 path) ----
__device__ __forceinline__ unsigned long long splat2(float v) {
    unsigned long long r;
    asm("mov.b64 %0, {%1, %1};" : "=l"(r) : "f"(v));
    return r;
}
__device__ __forceinline__ void fma2(unsigned long long &d, unsigned long long a,
                                     unsigned long long b) {
    asm("fma.rn.f32x2 %0, %1, %2, %0;" : "+l"(d) : "l"(a), "l"(b));
}
__device__ __forceinline__ float2 unpack2(unsigned long long v) {
    float2 f;
    asm("mov.b64 {%0, %1}, %2;" : "=f"(f.x), "=f"(f.y) : "l"(v));
    return f;
}
__device__ __forceinline__ unsigned long long pack2(float x, float y) {
    unsigned long long r;
    asm("mov.b64 %0, {%1, %2};" : "=l"(r) : "f"(x), "f"(y));
    return r;
}

extern "C" __global__ void __launch_bounds__(NTHREADS, 1)
tq_kernel(const float* __restrict__ x, const float* __restrict__ Pi,
          const float* __restrict__ cent, const float* __restrict__ bnd,
          float* __restrict__ out, int nrows, int ntiles)
{
    extern __shared__ char smem[];
    float* Pi_s = (float*)smem;                                       // [128][129]
    unsigned long long* Xs = (unsigned long long*)(smem + 66048);     // [128][130] pairs
    unsigned long long* Vs = Xs;                                      // in-place: warp-local rows
    float* inv2 = (float*)(smem + 66048 + 133120);                    // [256] 1/(norm+eps)
    float* nq2  = inv2 + 256;                                         // [256] fp16-roundtrip norm
    float* sI   = nq2 + 256;                                          // [15] interior boundaries
    float* sC   = sI + 16;                                            // [16] centroids

    const int t = threadIdx.x;
    const int w = t >> 5;
    const int l = t & 31;

    // ---------- one-time setup: tables + Pi staging (row-major, stride PJ) ----------
    if (t < 16) sC[t] = cent[t];
    if (t < 15) sI[t] = bnd[t + 1];
    {
        int j  = t >> 2;           // 0..127
        int k0 = (t & 3) * 32;     // quarter-row
        const float4* src = (const float4*)(Pi + j * D + k0);
        float* dst = Pi_s + j * PJ + k0;
        #pragma unroll
        for (int i = 0; i < 8; i++) {
            float4 v = src[i];
            dst[4 * i + 0] = v.x; dst[4 * i + 1] = v.y;
            dst[4 * i + 2] = v.z; dst[4 * i + 3] = v.w;
        }
    }
    __syncthreads();

    const int pg0    = w * P_W;         // this warp's 8 row-pairs
    const int r_loc  = t >> 1;          // staging: row in tile (0..255); warp-local: rows 16w..16w+15
    const int khalf  = (t & 1) * 64;    // staging: k half
    const int pg_st  = r_loc >> 1;
    const int half   = r_loc & 1;

    for (int tile = blockIdx.x; tile < ntiles; tile += gridDim.x) {
        const int row0 = tile * TILE_ROWS;

        // ---------- stage X tile (pair-interleaved ull layout) + row norms ----------
        {
            int row = row0 + r_loc;
            float s = 0.f;
            float* dstf = (float*)Xs;   // word index = (pair*XS_STRIDE + k)*2 + half
            if (row < nrows) {
                const float4* xr = (const float4*)(x + (size_t)row * D + khalf);
                #pragma unroll
                for (int i = 0; i < 16; i++) {
                    float4 v = xr[i];
                    s += v.x * v.x + v.y * v.y + v.z * v.z + v.w * v.w;
                    int base = ((pg_st * XS_STRIDE + khalf + 4 * i) << 1) + half;
                    dstf[base + 0] = v.x; dstf[base + 2] = v.y;
                    dstf[base + 4] = v.z; dstf[base + 6] = v.w;
                }
            } else {
                #pragma unroll
                for (int i = 0; i < 16; i++) {
                    int base = ((pg_st * XS_STRIDE + khalf + 4 * i) << 1) + half;
                    dstf[base + 0] = 0.f; dstf[base + 2] = 0.f;
                    dstf[base + 4] = 0.f; dstf[base + 6] = 0.f;
                }
            }
            s += __shfl_xor_sync(0xffffffffu, s, 1);
            if ((t & 1) == 0) {
                float norm = sqrtf(s);
                inv2[r_loc] = 1.0f / (norm + 1e-8f);
                nq2[r_loc]  = __half2float(__float2half_rn(norm));
            }
        }
        __syncwarp();

        // ---------- GEMM1: R[pair][j] = sum_k X[pair][k] * Pi[j][k],  j = l + 32*jj ----------
        unsigned long long acc[P_W][4];
        #pragma unroll
        for (int p = 0; p < P_W; p++)
            #pragma unroll
            for (int jj = 0; jj < 4; jj++) acc[p][jj] = 0ull;
        {
            const float* pr0 = Pi_s + (l +  0) * PJ;
            const float* pr1 = Pi_s + (l + 32) * PJ;
            const float* pr2 = Pi_s + (l + 64) * PJ;
            const float* pr3 = Pi_s + (l + 96) * PJ;
            #pragma unroll 2
            for (int k = 0; k < D; k += 2) {
                unsigned long long s00 = splat2(pr0[k]), s01 = splat2(pr0[k + 1]);
                unsigned long long s10 = splat2(pr1[k]), s11 = splat2(pr1[k + 1]);
                unsigned long long s20 = splat2(pr2[k]), s21 = splat2(pr2[k + 1]);
                unsigned long long s30 = splat2(pr3[k]), s31 = splat2(pr3[k + 1]);
                #pragma unroll
                for (int p = 0; p < P_W; p++) {
                    ulonglong2 xv = *(const ulonglong2*)(Xs + (pg0 + p) * XS_STRIDE + k);
                    fma2(acc[p][0], xv.x, s00); fma2(acc[p][0], xv.y, s01);
                    fma2(acc[p][1], xv.x, s10); fma2(acc[p][1], xv.y, s11);
                    fma2(acc[p][2], xv.x, s20); fma2(acc[p][2], xv.y, s21);
                    fma2(acc[p][3], xv.x, s30); fma2(acc[p][3], xv.y, s31);
                }
            }
        }
        __syncwarp();   // all GEMM1 reads of this warp's Xs rows complete before overwrite

        // ---------- quantize: scale by inv-norm, 4-level binary search; write V IN-PLACE ----------
        #pragma unroll
        for (int p = 0; p < P_W; p++) {
            int pg = pg0 + p;
            float ia = inv2[pg * 2 + 0];
            float ib = inv2[pg * 2 + 1];
            #pragma unroll
            for (int jj = 0; jj < 4; jj++) {
                float2 r2 = unpack2(acc[p][jj]);
                float va = r2.x * ia;
                float vb = r2.y * ib;
                int ida = (va > sI[7]) ? 8 : 0;
                ida += (va > sI[ida + 3]) ? 4 : 0;
                ida += (va > sI[ida + 1]) ? 2 : 0;
                ida += (va > sI[ida + 0]) ? 1 : 0;
                int idb = (vb > sI[7]) ? 8 : 0;
                idb += (vb > sI[idb + 3]) ? 4 : 0;
                idb += (vb > sI[idb + 1]) ? 2 : 0;
                idb += (vb > sI[idb + 0]) ? 1 : 0;
                Vs[pg * XS_STRIDE + l + 32 * jj] = pack2(sC[ida], sC[idb]);
            }
        }
        __syncwarp();

        // ---------- GEMM2: O[pair][k] = sum_j V[pair][j] * Pi[j][k],  k = l + 32*kk ----------
        unsigned long long acc2[P_W][4];
        #pragma unroll
        for (int p = 0; p < P_W; p++)
            #pragma unroll
            for (int kk = 0; kk < 4; kk++) acc2[p][kk] = 0ull;
        {
            #pragma unroll 2
            for (int j = 0; j < D; j += 2) {
                const float* pa = Pi_s + j * PJ + l;
                const float* pb = pa + PJ;
                unsigned long long t00 = splat2(pa[0]),  t01 = splat2(pb[0]);
                unsigned long long t10 = splat2(pa[32]), t11 = splat2(pb[32]);
                unsigned long long t20 = splat2(pa[64]), t21 = splat2(pb[64]);
                unsigned long long t30 = splat2(pa[96]), t31 = splat2(pb[96]);
                #pragma unroll
                for (int p = 0; p < P_W; p++) {
                    ulonglong2 vv = *(const ulonglong2*)(Vs + (pg0 + p) * XS_STRIDE + j);
                    fma2(acc2[p][0], vv.x, t00); fma2(acc2[p][0], vv.y, t01);
                    fma2(acc2[p][1], vv.x, t10); fma2(acc2[p][1], vv.y, t11);
                    fma2(acc2[p][2], vv.x, t20); fma2(acc2[p][2], vv.y, t21);
                    fma2(acc2[p][3], vv.x, t30); fma2(acc2[p][3], vv.y, t31);
                }
            }
        }

        // ---------- epilogue: rescale by fp16-roundtrip norm, coalesced STG.32 ----------
        #pragma unroll
        for (int p = 0; p < P_W; p++) {
            int pg = pg0 + p;
            float na = nq2[pg * 2 + 0];
            float nb = nq2[pg * 2 + 1];
            int rowA = row0 + pg * 2;
            int rowB = rowA + 1;
            float* oA = out + (size_t)rowA * D + l;
            float* oB = out + (size_t)rowB * D + l;
            #pragma unroll
            for (int kk = 0; kk < 4; kk++) {
                float2 c = unpack2(acc2[p][kk]);
                if (rowA < nrows) oA[32 * kk] = c.x * na;
                if (rowB < nrows) oB[32 * kk] = c.y * nb;
            }
        }
        __syncwarp();  // protect Xs/norms against next iteration's staging
    }
}

extern "C" void kernel_launch(void* const* d_in, const int* in_sizes, int n_in,
                              void* d_out, int out_size) {
    const float* x    = (const float*)d_in[0];
    const float* Pi   = (const float*)d_in[1];
    const float* cent = (const float*)d_in[2];
    const float* bnd  = (const float*)d_in[3];
    float* out = (float*)d_out;

    int nrows  = in_sizes[0] / D;
    int ntiles = (nrows + TILE_ROWS - 1) / TILE_ROWS;

    cudaFuncSetAttribute(tq_kernel, cudaFuncAttributeMaxDynamicSharedMemorySize,
                         SMEM_BYTES);

    int grid = ntiles < 148 ? ntiles : 148;  // persistent: 1 CTA/SM, Pi staged once
    tq_kernel<<<grid, NTHREADS, SMEM_BYTES>>>(x, Pi, cent, bnd, out, nrows, ntiles);
}

// round 10
// speedup vs baseline: 1.1929x; 1.0554x over previous
#include <cuda_runtime.h>
#include <cuda_bf16.h>
#include <cuda_fp16.h>
#include <mma.h>
#include <cstdint>

using namespace nvcuda;

#define D 128
#define TR 128            /* tile rows: 8 warps x 16 rows */
#define NTH 256
#define LDB 136           /* bf16 smem row stride (mult of 8, odd*8 -> conflict-free LDSM) */
#define LDS 20            /* f32 scratch stride */

/* ---- smem layout (bytes) ---- */
#define OFF_PI0 0                 /* Pi split hi  [128][136] bf16  34816B */
#define OFF_PI1 34816
#define OFF_PI2 69632
#define OFF_X0  104448            /* X split hi (V0 overwrites)    34816B */
#define OFF_X1  139264            /* X split mid (V1 overwrites)          */
#define OFF_X2  174080            /* X split lo                            */
#define OFF_SCR 208896            /* 8 warps x [2][16][20] f32 = 20480B    */
#define OFF_INV 229376            /* [128] f32 */
#define OFF_NQ  229888            /* [128] f32 */
#define OFF_SI  230400            /* [15] interior boundaries */
#define OFF_SC  230464            /* [16] centroids */
#define SMEM_BYTES 230528

__device__ __forceinline__ uint32_t b2u(__nv_bfloat162 v) {
    return *reinterpret_cast<uint32_t*>(&v);
}

/* split a float pair into 3 bf16x2 words (hi, mid, lo) */
__device__ __forceinline__ void split3(float f0, float f1,
                                       uint32_t &o0, uint32_t &o1, uint32_t &o2) {
    __nv_bfloat162 b0 = __floats2bfloat162_rn(f0, f1);
    float e0 = f0 - __low2float(b0), e1 = f1 - __high2float(b0);
    __nv_bfloat162 b1 = __floats2bfloat162_rn(e0, e1);
    float g0 = e0 - __low2float(b1), g1 = e1 - __high2float(b1);
    __nv_bfloat162 b2 = __floats2bfloat162_rn(g0, g1);
    o0 = b2u(b0); o1 = b2u(b1); o2 = b2u(b2);
}

typedef wmma::fragment<wmma::matrix_a, 16, 16, 16, __nv_bfloat16, wmma::row_major> FragA;
typedef wmma::fragment<wmma::matrix_b, 16, 16, 16, __nv_bfloat16, wmma::col_major> FragBC;
typedef wmma::fragment<wmma::matrix_b, 16, 16, 16, __nv_bfloat16, wmma::row_major> FragBR;
typedef wmma::fragment<wmma::accumulator, 16, 16, 16, float> FragC;

extern "C" __global__ void __launch_bounds__(NTH, 1)
tq_kernel(const float* __restrict__ x, const float* __restrict__ Pi,
          const float* __restrict__ cent, const float* __restrict__ bnd,
          float* __restrict__ out, int nrows, int ntiles)
{
    extern __shared__ char smem[];
    __nv_bfloat16* P0s = (__nv_bfloat16*)(smem + OFF_PI0);
    __nv_bfloat16* P1s = (__nv_bfloat16*)(smem + OFF_PI1);
    __nv_bfloat16* P2s = (__nv_bfloat16*)(smem + OFF_PI2);
    __nv_bfloat16* X0s = (__nv_bfloat16*)(smem + OFF_X0);
    __nv_bfloat16* X1s = (__nv_bfloat16*)(smem + OFF_X1);
    __nv_bfloat16* X2s = (__nv_bfloat16*)(smem + OFF_X2);
    float* INV = (float*)(smem + OFF_INV);
    float* NQ  = (float*)(smem + OFF_NQ);
    float* sI  = (float*)(smem + OFF_SI);
    float* sC  = (float*)(smem + OFF_SC);

    const int t = threadIdx.x;
    const int w = t >> 5;
    const int l = t & 31;

    if (t < 16) sC[t] = cent[t];
    if (t < 15) sI[t] = bnd[t + 1];

    /* ---- one-time: Pi 3-way bf16 split into smem [j][k], stride 136 ---- */
    {
        int j = t >> 1, k0 = (t & 1) * 64;
        for (int kk = 0; kk < 64; kk++) {
            int k = k0 + kk;
            float f = Pi[j * D + k];
            __nv_bfloat16 b0 = __float2bfloat16_rn(f);
            float e1 = f - __bfloat162float(b0);
            __nv_bfloat16 b1 = __float2bfloat16_rn(e1);
            float e2 = e1 - __bfloat162float(b1);
            P0s[j * LDB + k] = b0;
            P1s[j * LDB + k] = b1;
            P2s[j * LDB + k] = __float2bfloat16_rn(e2);
        }
    }
    __syncthreads();

    float* scr = (float*)(smem + OFF_SCR) + w * 640;   /* [2][16][20] per warp */
    const int rl = (w << 4) + (l >> 1);                /* this lane's row in tile */
    const int h2 = l & 1;

    for (int tile = blockIdx.x; tile < ntiles; tile += gridDim.x) {
        const int row0 = tile * TR;

        /* ---------- stage: gmem -> 3-way bf16 splits in smem + row norms ---------- */
        {
            int gr = row0 + rl;
            float s = 0.f;
            uint32_t* x0p = (uint32_t*)(X0s + rl * LDB + h2 * 64);
            uint32_t* x1p = (uint32_t*)(X1s + rl * LDB + h2 * 64);
            uint32_t* x2p = (uint32_t*)(X2s + rl * LDB + h2 * 64);
            if (gr < nrows) {
                const float4* src = (const float4*)(x + (size_t)gr * D + h2 * 64);
                #pragma unroll
                for (int i = 0; i < 16; i++) {
                    float4 v = src[i];
                    s += v.x * v.x + v.y * v.y + v.z * v.z + v.w * v.w;
                    uint32_t a0, a1, a2, c0, c1, c2;
                    split3(v.x, v.y, a0, a1, a2);
                    split3(v.z, v.w, c0, c1, c2);
                    x0p[2 * i] = a0;     x1p[2 * i] = a1;     x2p[2 * i] = a2;
                    x0p[2 * i + 1] = c0; x1p[2 * i + 1] = c1; x2p[2 * i + 1] = c2;
                }
            } else {
                #pragma unroll
                for (int i = 0; i < 32; i++) { x0p[i] = 0u; x1p[i] = 0u; x2p[i] = 0u; }
            }
            s += __shfl_xor_sync(0xffffffffu, s, 1);
            if (h2 == 0) {
                float nm = sqrtf(s);
                INV[rl] = 1.0f / (nm + 1e-8f);
                NQ[rl]  = __half2float(__float2half_rn(nm));
            }
        }
        __syncwarp();

        /* ---------- cache A fragments (X splits) in registers ---------- */
        FragA aX[3][8];
        #pragma unroll
        for (int kb = 0; kb < 8; kb++) {
            wmma::load_matrix_sync(aX[0][kb], X0s + (w * 16) * LDB + kb * 16, LDB);
            wmma::load_matrix_sync(aX[1][kb], X1s + (w * 16) * LDB + kb * 16, LDB);
            wmma::load_matrix_sync(aX[2][kb], X2s + (w * 16) * LDB + kb * 16, LDB);
        }
        __syncwarp();
        const float ivn = INV[rl];

        /* ---------- GEMM1 (6 split passes) + quantize, jb-pairs; V overwrites X0/X1 ---------- */
        #pragma unroll
        for (int jp = 0; jp < 4; jp++) {
            FragC accA, accB;
            wmma::fill_fragment(accA, 0.f);
            wmma::fill_fragment(accB, 0.f);
            #pragma unroll
            for (int kb = 0; kb < 8; kb++) {
                FragBC bA0, bA1, bA2, bB0, bB1, bB2;
                const __nv_bfloat16* pA = P0s + (2 * jp) * 16 * LDB + kb * 16;
                const __nv_bfloat16* pB = P0s + (2 * jp + 1) * 16 * LDB + kb * 16;
                wmma::load_matrix_sync(bA0, pA, LDB);
                wmma::load_matrix_sync(bA1, pA + (OFF_PI1 - OFF_PI0) / 2, LDB);
                wmma::load_matrix_sync(bA2, pA + (OFF_PI2 - OFF_PI0) / 2, LDB);
                wmma::load_matrix_sync(bB0, pB, LDB);
                wmma::load_matrix_sync(bB1, pB + (OFF_PI1 - OFF_PI0) / 2, LDB);
                wmma::load_matrix_sync(bB2, pB + (OFF_PI2 - OFF_PI0) / 2, LDB);
                wmma::mma_sync(accA, aX[0][kb], bA0, accA);
                wmma::mma_sync(accB, aX[0][kb], bB0, accB);
                wmma::mma_sync(accA, aX[0][kb], bA1, accA);
                wmma::mma_sync(accB, aX[0][kb], bB1, accB);
                wmma::mma_sync(accA, aX[1][kb], bA0, accA);
                wmma::mma_sync(accB, aX[1][kb], bB0, accB);
                wmma::mma_sync(accA, aX[1][kb], bA1, accA);
                wmma::mma_sync(accB, aX[1][kb], bB1, accB);
                wmma::mma_sync(accA, aX[0][kb], bA2, accA);
                wmma::mma_sync(accB, aX[0][kb], bB2, accB);
                wmma::mma_sync(accA, aX[2][kb], bA0, accA);
                wmma::mma_sync(accB, aX[2][kb], bB0, accB);
            }
            wmma::store_matrix_sync(scr,       accA, LDS, wmma::mem_row_major);
            wmma::store_matrix_sync(scr + 320, accB, LDS, wmma::mem_row_major);
            __syncwarp();
            #pragma unroll
            for (int hb = 0; hb < 2; hb++) {
                int jb = 2 * jp + hb;
                const float* sc2 = scr + hb * 320 + (l >> 1) * LDS + (l & 1) * 8;
                uint32_t* v0p = (uint32_t*)(X0s + rl * LDB + jb * 16 + (l & 1) * 8);
                uint32_t* v1p = (uint32_t*)(X1s + rl * LDB + jb * 16 + (l & 1) * 8);
                #pragma unroll
                for (int i = 0; i < 4; i++) {
                    float va = sc2[2 * i] * ivn;
                    float vb = sc2[2 * i + 1] * ivn;
                    int ida = (va > sI[7]) ? 8 : 0;
                    ida += (va > sI[ida + 3]) ? 4 : 0;
                    ida += (va > sI[ida + 1]) ? 2 : 0;
                    ida += (va > sI[ida + 0]) ? 1 : 0;
                    int idb = (vb > sI[7]) ? 8 : 0;
                    idb += (vb > sI[idb + 3]) ? 4 : 0;
                    idb += (vb > sI[idb + 1]) ? 2 : 0;
                    idb += (vb > sI[idb + 0]) ? 1 : 0;
                    float ca = sC[ida], cb = sC[idb];
                    __nv_bfloat162 b0 = __floats2bfloat162_rn(ca, cb);
                    float e0 = ca - __low2float(b0), e1 = cb - __high2float(b0);
                    __nv_bfloat162 b1 = __floats2bfloat162_rn(e0, e1);
                    v0p[i] = b2u(b0);
                    v1p[i] = b2u(b1);
                }
            }
            __syncwarp();
        }

        /* ---------- cache V fragments ---------- */
        FragA aV[2][8];
        #pragma unroll
        for (int jb = 0; jb < 8; jb++) {
            wmma::load_matrix_sync(aV[0][jb], X0s + (w * 16) * LDB + jb * 16, LDB);
            wmma::load_matrix_sync(aV[1][jb], X1s + (w * 16) * LDB + jb * 16, LDB);
        }
        const float nqv = NQ[rl];
        const int gr = row0 + rl;

        /* ---------- GEMM2 (3 split passes) + epilogue, kb-pairs ---------- */
        #pragma unroll
        for (int kp = 0; kp < 4; kp++) {
            FragC acA, acB;
            wmma::fill_fragment(acA, 0.f);
            wmma::fill_fragment(acB, 0.f);
            #pragma unroll
            for (int jb = 0; jb < 8; jb++) {
                FragBR bA0, bA1, bB0, bB1;
                const __nv_bfloat16* pA = P0s + jb * 16 * LDB + (2 * kp) * 16;
                const __nv_bfloat16* pB = P0s + jb * 16 * LDB + (2 * kp + 1) * 16;
                wmma::load_matrix_sync(bA0, pA, LDB);
                wmma::load_matrix_sync(bA1, pA + (OFF_PI1 - OFF_PI0) / 2, LDB);
                wmma::load_matrix_sync(bB0, pB, LDB);
                wmma::load_matrix_sync(bB1, pB + (OFF_PI1 - OFF_PI0) / 2, LDB);
                wmma::mma_sync(acA, aV[0][jb], bA0, acA);
                wmma::mma_sync(acB, aV[0][jb], bB0, acB);
                wmma::mma_sync(acA, aV[0][jb], bA1, acA);
                wmma::mma_sync(acB, aV[0][jb], bB1, acB);
                wmma::mma_sync(acA, aV[1][jb], bA0, acA);
                wmma::mma_sync(acB, aV[1][jb], bB0, acB);
            }
            wmma::store_matrix_sync(scr,       acA, LDS, wmma::mem_row_major);
            wmma::store_matrix_sync(scr + 320, acB, LDS, wmma::mem_row_major);
            __syncwarp();
            if (gr < nrows) {
                const float* s0 = scr + (l >> 1) * LDS + (l & 1) * 8;
                const float* s1 = s0 + 320;
                float* op = out + (size_t)gr * D + kp * 32 + (l & 1) * 8;
                float4 o;
                o = make_float4(s0[0] * nqv, s0[1] * nqv, s0[2] * nqv, s0[3] * nqv);
                *(float4*)op = o;
                o = make_float4(s0[4] * nqv, s0[5] * nqv, s0[6] * nqv, s0[7] * nqv);
                *(float4*)(op + 4) = o;
                o = make_float4(s1[0] * nqv, s1[1] * nqv, s1[2] * nqv, s1[3] * nqv);
                *(float4*)(op + 16) = o;
                o = make_float4(s1[4] * nqv, s1[5] * nqv, s1[6] * nqv, s1[7] * nqv);
                *(float4*)(op + 20) = o;
            }
            __syncwarp();
        }
        __syncwarp();
    }
}

extern "C" void kernel_launch(void* const* d_in, const int* in_sizes, int n_in,
                              void* d_out, int out_size) {
    const float* x    = (const float*)d_in[0];
    const float* Pi   = (const float*)d_in[1];
    const float* cent = (const float*)d_in[2];
    const float* bnd  = (const float*)d_in[3];
    float* out = (float*)d_out;

    int nrows  = in_sizes[0] / D;
    int ntiles = (nrows + TR - 1) / TR;

    cudaFuncSetAttribute(tq_kernel, cudaFuncAttributeMaxDynamicSharedMemorySize,
                         SMEM_BYTES);

    int grid = ntiles < 148 ? ntiles : 148;  /* persistent: 1 CTA/SM */
    tq_kernel<<<grid, NTH, SMEM_BYTES>>>(x, Pi, cent, bnd, out, nrows, ntiles);
}